// round 6
// baseline (speedup 1.0000x reference)
#include <cuda_runtime.h>
#include <cuda_bf16.h>
#include <cstdint>
#include <math.h>

// Problem constants
#define BATCH 2
#define SEQ   2048
#define EMB   2048
#define NHEAD 16
#define DHEAD 128
#define NEXP_ 64
#define RLORA 32
#define ROWS  4096          // BATCH*SEQ
#define KAUG  2144          // EMB + RLORA + NEXP_

// ---------------- scratch (static device globals; no allocations) ----------
__device__ float g_q[(size_t)ROWS * EMB];
__device__ float g_k[(size_t)ROWS * EMB];
__device__ float g_v[(size_t)ROWS * EMB];
__device__ float g_att[(size_t)ROWS * EMB];
// bf16 hi/lo presplit buffers
__device__ __nv_bfloat16 g_ah[(size_t)ROWS * EMB];          // activation hi
__device__ __nv_bfloat16 g_al[(size_t)ROWS * EMB];          // activation lo
__device__ __nv_bfloat16 g_hh[4][(size_t)ROWS * 96];        // haux hi per proj
__device__ __nv_bfloat16 g_hl[4][(size_t)ROWS * 96];        // haux lo per proj
__device__ __nv_bfloat16 g_wh[(size_t)4 * 2048 * KAUG];     // weights hi [W|B|R]
__device__ __nv_bfloat16 g_wl[(size_t)4 * 2048 * KAUG];     // weights lo

// ---------------------------------------------------------------------------
// helpers
// ---------------------------------------------------------------------------
__device__ __forceinline__ unsigned pack_bf2(__nv_bfloat16 a, __nv_bfloat16 b) {
    return (unsigned)__bfloat16_as_ushort(a) | ((unsigned)__bfloat16_as_ushort(b) << 16);
}
__device__ __forceinline__ void split_bf(float x, __nv_bfloat16& hi, __nv_bfloat16& lo) {
    hi = __float2bfloat16_rn(x);
    lo = __float2bfloat16_rn(x - __bfloat162float(hi));
}
__device__ __forceinline__ void mma_bf16(float* c, const unsigned* a, const unsigned* b) {
    asm volatile(
        "mma.sync.aligned.m16n8k16.row.col.f32.bf16.bf16.f32 "
        "{%0,%1,%2,%3}, {%4,%5,%6,%7}, {%8,%9}, {%0,%1,%2,%3};"
        : "+f"(c[0]), "+f"(c[1]), "+f"(c[2]), "+f"(c[3])
        : "r"(a[0]), "r"(a[1]), "r"(a[2]), "r"(a[3]), "r"(b[0]), "r"(b[1]));
}
__device__ __forceinline__ void cp_async16(unsigned* dst_smem, const void* src) {
    unsigned d = (unsigned)__cvta_generic_to_shared(dst_smem);
    asm volatile("cp.async.cg.shared.global [%0], [%1], 16;\n" :: "r"(d), "l"(src) : "memory");
}
#define CP_COMMIT asm volatile("cp.async.commit_group;\n" ::: "memory")

// ---------------------------------------------------------------------------
// pack_act: fp32 activation -> bf16 hi/lo
// ---------------------------------------------------------------------------
__global__ void pack_act(const float* __restrict__ src,
                         __nv_bfloat16* __restrict__ dh,
                         __nv_bfloat16* __restrict__ dl)
{
    int i = blockIdx.x * blockDim.x + threadIdx.x;   // over ROWS*EMB/4
    float4 v = *(const float4*)(src + 4 * (size_t)i);
    __nv_bfloat16 h0, l0, h1, l1, h2, l2, h3, l3;
    split_bf(v.x, h0, l0); split_bf(v.y, h1, l1);
    split_bf(v.z, h2, l2); split_bf(v.w, h3, l3);
    *(uint2*)(dh + 4 * (size_t)i) = make_uint2(pack_bf2(h0, h1), pack_bf2(h2, h3));
    *(uint2*)(dl + 4 * (size_t)i) = make_uint2(pack_bf2(l0, l1), pack_bf2(l2, l3));
}

// ---------------------------------------------------------------------------
// pack_w: concat [W | Bl | Rr] rows -> bf16 hi/lo, uniform KAUG stride.
// grid (2048 rows, 4 projs), 256 threads.
// ---------------------------------------------------------------------------
__global__ void pack_w(
    const float* __restrict__ W0, const float* __restrict__ B0, const float* __restrict__ R0,
    const float* __restrict__ W1, const float* __restrict__ B1, const float* __restrict__ R1,
    const float* __restrict__ W2, const float* __restrict__ B2, const float* __restrict__ R2,
    const float* __restrict__ W3, const float* __restrict__ B3, const float* __restrict__ R3,
    __nv_bfloat16* __restrict__ wh, __nv_bfloat16* __restrict__ wl)
{
    const int n = blockIdx.x, p = blockIdx.y;
    const float* W = (p == 0) ? W0 : (p == 1) ? W1 : (p == 2) ? W2 : W3;
    const float* Bm = (p == 0) ? B0 : (p == 1) ? B1 : (p == 2) ? B2 : B3;
    const float* Rm = (p == 0) ? R0 : (p == 1) ? R1 : (p == 2) ? R2 : R3;
    __nv_bfloat16* dh = wh + ((size_t)p * 2048 + n) * KAUG;
    __nv_bfloat16* dl = wl + ((size_t)p * 2048 + n) * KAUG;

    for (int k = threadIdx.x * 4; k < KAUG; k += 1024) {
        float4 v;
        if (k < EMB)              v = *(const float4*)(W + (size_t)n * EMB + k);
        else if (k < EMB + RLORA) v = *(const float4*)(Bm + (size_t)n * RLORA + (k - EMB));
        else                      v = *(const float4*)(Rm + (size_t)n * NEXP_ + (k - EMB - RLORA));
        __nv_bfloat16 h0, l0, h1, l1, h2, l2, h3, l3;
        split_bf(v.x, h0, l0); split_bf(v.y, h1, l1);
        split_bf(v.z, h2, l2); split_bf(v.w, h3, l3);
        *(uint2*)(dh + k) = make_uint2(pack_bf2(h0, h1), pack_bf2(h2, h3));
        *(uint2*)(dl + k) = make_uint2(pack_bf2(l0, l1), pack_bf2(l2, l3));
    }
}

// ---------------------------------------------------------------------------
// aux GEMM: h[row, 0:32]  = silu(x@A^T), h[row, 32:96] = silu(x@C^T)*mask
// epilogue writes bf16 hi/lo directly.
// ---------------------------------------------------------------------------
__global__ __launch_bounds__(256) void aux_gemm(
    const float* __restrict__ act, const float* __restrict__ mask,
    const float* __restrict__ A0, const float* __restrict__ C0,
    const float* __restrict__ A1, const float* __restrict__ C1,
    const float* __restrict__ A2, const float* __restrict__ C2,
    __nv_bfloat16* __restrict__ hh0, __nv_bfloat16* __restrict__ hl0,
    __nv_bfloat16* __restrict__ hh1, __nv_bfloat16* __restrict__ hl1,
    __nv_bfloat16* __restrict__ hh2, __nv_bfloat16* __restrict__ hl2)
{
    __shared__ float As[16][132];
    __shared__ float Bs[16][100];

    const int proj = blockIdx.x;
    const int m0 = blockIdx.y * 128;
    const float* A = (proj == 0) ? A0 : ((proj == 1) ? A1 : A2);
    const float* C = (proj == 0) ? C0 : ((proj == 1) ? C1 : C2);
    __nv_bfloat16* hh = (proj == 0) ? hh0 : ((proj == 1) ? hh1 : hh2);
    __nv_bfloat16* hl = (proj == 0) ? hl0 : ((proj == 1) ? hl1 : hl2);

    const int tid = threadIdx.x;
    const int ty = tid >> 4, tx = tid & 15;

    float acc[8][6];
    #pragma unroll
    for (int i = 0; i < 8; i++)
        #pragma unroll
        for (int j = 0; j < 6; j++) acc[i][j] = 0.f;

    for (int k0 = 0; k0 < EMB; k0 += 16) {
        #pragma unroll
        for (int i = 0; i < 2; i++) {
            int lin = tid + 256 * i;
            int r = lin >> 2, c4 = (lin & 3) << 2;
            float4 va = *(const float4*)(act + (size_t)(m0 + r) * EMB + k0 + c4);
            As[c4 + 0][r] = va.x; As[c4 + 1][r] = va.y;
            As[c4 + 2][r] = va.z; As[c4 + 3][r] = va.w;
        }
        #pragma unroll
        for (int i = 0; i < 2; i++) {
            int lin = tid + 256 * i;
            if (lin < 384) {
                int r = lin >> 2, c4 = (lin & 3) << 2;
                const float* src = (r < 32) ? (A + (size_t)r * EMB)
                                            : (C + (size_t)(r - 32) * EMB);
                float4 vb = *(const float4*)(src + k0 + c4);
                Bs[c4 + 0][r] = vb.x; Bs[c4 + 1][r] = vb.y;
                Bs[c4 + 2][r] = vb.z; Bs[c4 + 3][r] = vb.w;
            }
        }
        __syncthreads();

        #pragma unroll
        for (int kk = 0; kk < 16; kk++) {
            float a[8], b[6];
            *(float4*)&a[0] = *(const float4*)&As[kk][ty * 8];
            *(float4*)&a[4] = *(const float4*)&As[kk][ty * 8 + 4];
            #pragma unroll
            for (int j = 0; j < 6; j++) b[j] = Bs[kk][tx * 6 + j];
            #pragma unroll
            for (int i = 0; i < 8; i++)
                #pragma unroll
                for (int j = 0; j < 6; j++)
                    acc[i][j] += a[i] * b[j];
        }
        __syncthreads();
    }

    #pragma unroll
    for (int i = 0; i < 8; i++) {
        int row = m0 + ty * 8 + i;
        #pragma unroll
        for (int j = 0; j < 6; j++) {
            int u = tx * 6 + j;
            float v = acc[i][j];
            float s = v / (1.f + expf(-v));            // silu
            if (u >= 32) s *= mask[(size_t)row * NEXP_ + (u - 32)];
            __nv_bfloat16 hi, lo;
            split_bf(s, hi, lo);
            hh[(size_t)row * 96 + u] = hi;
            hl[(size_t)row * 96 + u] = lo;
        }
    }
}

// ---------------------------------------------------------------------------
// K-augmented GEMM on tensor cores: presplit bf16 inputs, cp.async 3-stage
// pipeline, K=16 stages. Block 128x128, 8 warps (4m x 2n), warp tile 32x64.
// ---------------------------------------------------------------------------
#define KST 16
#define NST 3
#define AP  12                 // words per smem row (8 data + 4 pad)
#define STW (128 * AP)         // words per array per stage
#define GSM_BYTES (NST * 4 * STW * 4)   // 73728

__global__ __launch_bounds__(256, 2) void gemm_mma(
    const __nv_bfloat16* __restrict__ acth, const __nv_bfloat16* __restrict__ actl,
    const __nv_bfloat16* __restrict__ hh,   const __nv_bfloat16* __restrict__ hl,
    const __nv_bfloat16* __restrict__ wh,   const __nv_bfloat16* __restrict__ wl,
    const float* __restrict__ bias, float* __restrict__ out)
{
    extern __shared__ unsigned smem[];
    const int tid = threadIdx.x;
    const int lane = tid & 31, wid = tid >> 5;
    const int l4 = lane >> 2, lk = lane & 3;
    const int warp_m = wid & 3, warp_n = wid >> 2;
    const int m0 = blockIdx.y * 128, n0 = blockIdx.x * 128;

    const int r = tid >> 1, ch = tid & 1;
    const int dstw = r * AP + ch * 4;

    float c[2][8][4];
    #pragma unroll
    for (int mt = 0; mt < 2; mt++)
        #pragma unroll
        for (int nt = 0; nt < 8; nt++)
            #pragma unroll
            for (int i = 0; i < 4; i++) c[mt][nt][i] = 0.f;

#define FILL(S_IDX, K0) do {                                                   \
    int s_ = (S_IDX); int k0_ = (K0);                                          \
    const __nv_bfloat16 *pah_, *pal_;                                          \
    if (k0_ < EMB) {                                                           \
        pah_ = acth + (size_t)(m0 + r) * EMB + k0_ + ch * 8;                   \
        pal_ = actl + (size_t)(m0 + r) * EMB + k0_ + ch * 8;                   \
    } else {                                                                   \
        pah_ = hh + (size_t)(m0 + r) * 96 + (k0_ - EMB) + ch * 8;              \
        pal_ = hl + (size_t)(m0 + r) * 96 + (k0_ - EMB) + ch * 8;              \
    }                                                                          \
    cp_async16(smem + (s_ * 4 + 0) * STW + dstw, pah_);                        \
    cp_async16(smem + (s_ * 4 + 1) * STW + dstw, pal_);                        \
    cp_async16(smem + (s_ * 4 + 2) * STW + dstw,                               \
               wh + (size_t)(n0 + r) * KAUG + k0_ + ch * 8);                   \
    cp_async16(smem + (s_ * 4 + 3) * STW + dstw,                               \
               wl + (size_t)(n0 + r) * KAUG + k0_ + ch * 8);                   \
} while (0)

    FILL(0, 0);   CP_COMMIT;
    FILL(1, KST); CP_COMMIT;

    const int NSQ = KAUG / KST;   // 134
    for (int ks = 0; ks < NSQ; ks++) {
        asm volatile("cp.async.wait_group 1;\n" ::: "memory");
        __syncthreads();

        int nf = ks + NST - 1;
        if (nf < NSQ) FILL(nf % NST, nf * KST);
        CP_COMMIT;   // empty group in tail iterations keeps wait counting valid

        const unsigned* Ah  = smem + ((ks % NST) * 4 + 0) * STW;
        const unsigned* Al  = smem + ((ks % NST) * 4 + 1) * STW;
        const unsigned* Bh  = smem + ((ks % NST) * 4 + 2) * STW;
        const unsigned* Blo = smem + ((ks % NST) * 4 + 3) * STW;

        unsigned ah[2][4], al[2][4];
        #pragma unroll
        for (int mt = 0; mt < 2; mt++) {
            int rb = warp_m * 32 + mt * 16 + l4;
            ah[mt][0] = Ah[rb * AP + lk];
            ah[mt][1] = Ah[(rb + 8) * AP + lk];
            ah[mt][2] = Ah[rb * AP + 4 + lk];
            ah[mt][3] = Ah[(rb + 8) * AP + 4 + lk];
            al[mt][0] = Al[rb * AP + lk];
            al[mt][1] = Al[(rb + 8) * AP + lk];
            al[mt][2] = Al[rb * AP + 4 + lk];
            al[mt][3] = Al[(rb + 8) * AP + 4 + lk];
        }
        #pragma unroll
        for (int nt = 0; nt < 8; nt++) {
            int cb = warp_n * 64 + nt * 8 + l4;
            unsigned bh[2], bl[2];
            bh[0] = Bh[cb * AP + lk];
            bh[1] = Bh[cb * AP + 4 + lk];
            bl[0] = Blo[cb * AP + lk];
            bl[1] = Blo[cb * AP + 4 + lk];
            #pragma unroll
            for (int mt = 0; mt < 2; mt++) {
                mma_bf16(c[mt][nt], ah[mt], bh);
                mma_bf16(c[mt][nt], ah[mt], bl);
                mma_bf16(c[mt][nt], al[mt], bh);
            }
        }
    }
#undef FILL

    float2 bv[8];
    #pragma unroll
    for (int nt = 0; nt < 8; nt++) {
        int col = n0 + warp_n * 64 + nt * 8 + 2 * lk;
        if (bias) bv[nt] = *(const float2*)(bias + col);
        else      bv[nt] = make_float2(0.f, 0.f);
    }
    #pragma unroll
    for (int mt = 0; mt < 2; mt++) {
        int r0 = m0 + warp_m * 32 + mt * 16 + l4;
        #pragma unroll
        for (int nt = 0; nt < 8; nt++) {
            int col = n0 + warp_n * 64 + nt * 8 + 2 * lk;
            float2 o0 = make_float2(c[mt][nt][0] + bv[nt].x, c[mt][nt][1] + bv[nt].y);
            float2 o1 = make_float2(c[mt][nt][2] + bv[nt].x, c[mt][nt][3] + bv[nt].y);
            *(float2*)(out + (size_t)r0 * EMB + col)       = o0;
            *(float2*)(out + (size_t)(r0 + 8) * EMB + col) = o1;
        }
    }
}

// ---------------------------------------------------------------------------
// RoPE (in-place on q and k)
// ---------------------------------------------------------------------------
__global__ void rope_kernel(float* __restrict__ q, float* __restrict__ k)
{
    int idx = blockIdx.x * blockDim.x + threadIdx.x;   // ROWS*NHEAD*64
    if (idx >= ROWS * NHEAD * 64) return;
    int j   = idx & 63;
    int h   = (idx >> 6) & 15;
    int row = idx >> 10;
    int s   = row & (SEQ - 1);

    float e   = (float)(2 * j) * (1.0f / 128.0f);
    float inv = powf(10000.0f, -e);
    float ang = (float)s * inv;
    float sn, cs;
    sincosf(ang, &sn, &cs);

    size_t base = (size_t)row * EMB + h * DHEAD + j;
    float x1 = q[base], x2 = q[base + 64];
    q[base]      = x1 * cs - x2 * sn;
    q[base + 64] = x2 * cs + x1 * sn;
    x1 = k[base]; x2 = k[base + 64];
    k[base]      = x1 * cs - x2 * sn;
    k[base + 64] = x2 * cs + x1 * sn;
}

// ---------------------------------------------------------------------------
// Causal flash attention on tensor cores (split-bf16).
// ---------------------------------------------------------------------------
#define KPP 68
#define VPP 136
#define FA2_SMEM ((64 * KPP * 2 + 32 * VPP * 2) * 4)

__global__ __launch_bounds__(256) void flash_mma(
    const float* __restrict__ q, const float* __restrict__ k,
    const float* __restrict__ v, float* __restrict__ o)
{
    extern __shared__ unsigned sw[];
    unsigned* Kph = sw;
    unsigned* Kpl = Kph + 64 * KPP;
    unsigned* Vph = Kpl + 64 * KPP;
    unsigned* Vpl = Vph + 32 * VPP;

    const int tid = threadIdx.x;
    const int lane = tid & 31, wm = tid >> 5;
    const int l4 = lane >> 2, lk = lane & 3;
    const int iblk = (int)gridDim.x - 1 - (int)blockIdx.x;   // heavy CTAs first
    const int bh = blockIdx.y;
    const int b = bh >> 4, h = bh & 15;
    const size_t rowbase = (size_t)b * SEQ;
    const int m0 = iblk * 128;
    const float scale = 0.08838834764831845f;    // 1/sqrt(128)

    unsigned qh[8][4], ql[8][4];
    {
        const int r0 = m0 + wm * 16 + l4;
        #pragma unroll
        for (int s = 0; s < 8; s++) {
            #pragma unroll
            for (int f = 0; f < 4; f++) {
                int r = r0 + ((f & 1) ? 8 : 0);
                int d = 16 * s + 2 * lk + ((f & 2) ? 8 : 0);
                float2 qv = *(const float2*)(q + (rowbase + r) * EMB + h * DHEAD + d);
                float x = qv.x * scale, y = qv.y * scale;
                __nv_bfloat16 hx, lx, hy, ly;
                split_bf(x, hx, lx); split_bf(y, hy, ly);
                qh[s][f] = pack_bf2(hx, hy);
                ql[s][f] = pack_bf2(lx, ly);
            }
        }
    }

    float mr0 = -1e30f, mr1 = -1e30f, lr0 = 0.f, lr1 = 0.f;
    float oacc[16][4];
    #pragma unroll
    for (int nt = 0; nt < 16; nt++)
        #pragma unroll
        for (int i = 0; i < 4; i++) oacc[nt][i] = 0.f;

    const int ntiles = 2 * iblk + 2;
    for (int j = 0; j < ntiles; j++) {
        #pragma unroll
        for (int i = 0; i < 16; i++) {
            int lin = tid + 256 * i;
            int n = lin >> 6, dw = lin & 63;
            float2 kv = *(const float2*)(k + (rowbase + j * 64 + n) * EMB + h * DHEAD + 2 * dw);
            __nv_bfloat16 hx, lx, hy, ly;
            split_bf(kv.x, hx, lx); split_bf(kv.y, hy, ly);
            Kph[n * KPP + dw] = pack_bf2(hx, hy);
            Kpl[n * KPP + dw] = pack_bf2(lx, ly);
        }
        #pragma unroll
        for (int i = 0; i < 16; i++) {
            int lin = tid + 256 * i;
            int kw = lin >> 7, nn = lin & 127;
            size_t rbase = (rowbase + j * 64 + 2 * kw) * EMB + h * DHEAD + nn;
            float v0 = v[rbase];
            float v1 = v[rbase + EMB];
            __nv_bfloat16 h0, l0, h1, l1;
            split_bf(v0, h0, l0); split_bf(v1, h1, l1);
            Vph[kw * VPP + nn] = pack_bf2(h0, h1);
            Vpl[kw * VPP + nn] = pack_bf2(l0, l1);
        }
        __syncthreads();

        float sacc[8][4];
        #pragma unroll
        for (int nt = 0; nt < 8; nt++)
            #pragma unroll
            for (int i = 0; i < 4; i++) sacc[nt][i] = 0.f;

        #pragma unroll
        for (int s = 0; s < 8; s++) {
            #pragma unroll
            for (int nt = 0; nt < 8; nt++) {
                int kr = (nt * 8 + l4) * KPP + 8 * s + lk;
                unsigned b_hi[2], b_lo[2];
                b_hi[0] = Kph[kr];
                b_hi[1] = Kph[kr + 4];
                b_lo[0] = Kpl[kr];
                b_lo[1] = Kpl[kr + 4];
                mma_bf16(sacc[nt], qh[s], b_hi);
                mma_bf16(sacc[nt], qh[s], b_lo);
                mma_bf16(sacc[nt], ql[s], b_hi);
            }
        }

        if (j >= 2 * iblk) {
            int row0 = m0 + wm * 16 + l4;
            #pragma unroll
            for (int nt = 0; nt < 8; nt++) {
                int col = j * 64 + nt * 8 + 2 * lk;
                if (col     > row0)     sacc[nt][0] = -1e30f;
                if (col + 1 > row0)     sacc[nt][1] = -1e30f;
                if (col     > row0 + 8) sacc[nt][2] = -1e30f;
                if (col + 1 > row0 + 8) sacc[nt][3] = -1e30f;
            }
        }

        float mx0 = -1e30f, mx1 = -1e30f;
        #pragma unroll
        for (int nt = 0; nt < 8; nt++) {
            mx0 = fmaxf(mx0, fmaxf(sacc[nt][0], sacc[nt][1]));
            mx1 = fmaxf(mx1, fmaxf(sacc[nt][2], sacc[nt][3]));
        }
        mx0 = fmaxf(mx0, __shfl_xor_sync(0xffffffffu, mx0, 1));
        mx0 = fmaxf(mx0, __shfl_xor_sync(0xffffffffu, mx0, 2));
        mx1 = fmaxf(mx1, __shfl_xor_sync(0xffffffffu, mx1, 1));
        mx1 = fmaxf(mx1, __shfl_xor_sync(0xffffffffu, mx1, 2));

        float mn0 = fmaxf(mr0, mx0), mn1 = fmaxf(mr1, mx1);
        float al0 = __expf(mr0 - mn0), al1 = __expf(mr1 - mn1);
        mr0 = mn0; mr1 = mn1;

        unsigned ph01[8], pl01[8], ph23[8], pl23[8];
        float rs0 = 0.f, rs1 = 0.f;
        #pragma unroll
        for (int nt = 0; nt < 8; nt++) {
            float p0 = __expf(sacc[nt][0] - mn0);
            float p1 = __expf(sacc[nt][1] - mn0);
            float p2 = __expf(sacc[nt][2] - mn1);
            float p3 = __expf(sacc[nt][3] - mn1);
            rs0 += p0 + p1; rs1 += p2 + p3;
            __nv_bfloat16 h0, l0, h1, l1;
            split_bf(p0, h0, l0); split_bf(p1, h1, l1);
            ph01[nt] = pack_bf2(h0, h1); pl01[nt] = pack_bf2(l0, l1);
            split_bf(p2, h0, l0); split_bf(p3, h1, l1);
            ph23[nt] = pack_bf2(h0, h1); pl23[nt] = pack_bf2(l0, l1);
        }
        rs0 += __shfl_xor_sync(0xffffffffu, rs0, 1);
        rs0 += __shfl_xor_sync(0xffffffffu, rs0, 2);
        rs1 += __shfl_xor_sync(0xffffffffu, rs1, 1);
        rs1 += __shfl_xor_sync(0xffffffffu, rs1, 2);
        lr0 = lr0 * al0 + rs0;
        lr1 = lr1 * al1 + rs1;

        #pragma unroll
        for (int nt = 0; nt < 16; nt++) {
            oacc[nt][0] *= al0; oacc[nt][1] *= al0;
            oacc[nt][2] *= al1; oacc[nt][3] *= al1;
        }

        #pragma unroll
        for (int t = 0; t < 4; t++) {
            unsigned pa_h[4], pa_l[4];
            pa_h[0] = ph01[2 * t];     pa_l[0] = pl01[2 * t];
            pa_h[1] = ph23[2 * t];     pa_l[1] = pl23[2 * t];
            pa_h[2] = ph01[2 * t + 1]; pa_l[2] = pl01[2 * t + 1];
            pa_h[3] = ph23[2 * t + 1]; pa_l[3] = pl23[2 * t + 1];
            #pragma unroll
            for (int nt = 0; nt < 16; nt++) {
                int vr = (8 * t + lk) * VPP + nt * 8 + l4;
                unsigned b_hi[2], b_lo[2];
                b_hi[0] = Vph[vr];
                b_hi[1] = Vph[vr + 4 * VPP];
                b_lo[0] = Vpl[vr];
                b_lo[1] = Vpl[vr + 4 * VPP];
                mma_bf16(oacc[nt], pa_h, b_hi);
                mma_bf16(oacc[nt], pa_l, b_hi);
                mma_bf16(oacc[nt], pa_h, b_lo);
            }
        }
        __syncthreads();
    }

    float il0 = 1.f / lr0, il1 = 1.f / lr1;
    int row0 = m0 + wm * 16 + l4;
    #pragma unroll
    for (int nt = 0; nt < 16; nt++) {
        int col = h * DHEAD + nt * 8 + 2 * lk;
        float2 o0 = make_float2(oacc[nt][0] * il0, oacc[nt][1] * il0);
        float2 o1 = make_float2(oacc[nt][2] * il1, oacc[nt][3] * il1);
        *(float2*)(o + (rowbase + row0) * EMB + col)     = o0;
        *(float2*)(o + (rowbase + row0 + 8) * EMB + col) = o1;
    }
}

// ---------------------------------------------------------------------------
extern "C" void kernel_launch(void* const* d_in, const int* in_sizes, int n_in,
                              void* d_out, int out_size)
{
    const float* x    = (const float*)d_in[0];
    const float* mask = (const float*)d_in[1];
    const float* Wq = (const float*)d_in[2];  const float* bq = (const float*)d_in[3];
    const float* Aq = (const float*)d_in[4];  const float* Bq = (const float*)d_in[5];
    const float* Cq = (const float*)d_in[6];  const float* Rq = (const float*)d_in[7];
    const float* Wk = (const float*)d_in[8];  const float* bk = (const float*)d_in[9];
    const float* Ak = (const float*)d_in[10]; const float* Bk = (const float*)d_in[11];
    const float* Ck = (const float*)d_in[12]; const float* Rk = (const float*)d_in[13];
    const float* Wv = (const float*)d_in[14]; const float* bv = (const float*)d_in[15];
    const float* Av = (const float*)d_in[16]; const float* Bv = (const float*)d_in[17];
    const float* Cv = (const float*)d_in[18]; const float* Rv = (const float*)d_in[19];
    const float* Wo = (const float*)d_in[20]; const float* Ao = (const float*)d_in[21];
    const float* Bo = (const float*)d_in[22]; const float* Co = (const float*)d_in[23];
    const float* Ro = (const float*)d_in[24];

    float *q, *k, *v, *att;
    __nv_bfloat16 *ah, *al, *hh, *hl, *wh, *wl;
    cudaGetSymbolAddress((void**)&q,   g_q);
    cudaGetSymbolAddress((void**)&k,   g_k);
    cudaGetSymbolAddress((void**)&v,   g_v);
    cudaGetSymbolAddress((void**)&att, g_att);
    cudaGetSymbolAddress((void**)&ah,  g_ah);
    cudaGetSymbolAddress((void**)&al,  g_al);
    cudaGetSymbolAddress((void**)&hh,  g_hh);
    cudaGetSymbolAddress((void**)&hl,  g_hl);
    cudaGetSymbolAddress((void**)&wh,  g_wh);
    cudaGetSymbolAddress((void**)&wl,  g_wl);

    cudaFuncSetAttribute(flash_mma,
                         cudaFuncAttributeMaxDynamicSharedMemorySize, FA2_SMEM);
    cudaFuncSetAttribute(gemm_mma,
                         cudaFuncAttributeMaxDynamicSharedMemorySize, GSM_BYTES);

    const size_t HSTRIDE = (size_t)ROWS * 96;
    const size_t WSTRIDE = (size_t)2048 * KAUG;
    dim3 ggrid(EMB / 128, ROWS / 128);   // (16, 32)

    // presplit weights (all 4 projections)
    pack_w<<<dim3(2048, 4), 256>>>(Wq, Bq, Rq, Wk, Bk, Rk, Wv, Bv, Rv, Wo, Bo, Ro, wh, wl);
    // aux terms for q/k/v (bf16 hi/lo out)
    aux_gemm<<<dim3(3, ROWS / 128), 256>>>(x, mask, Aq, Cq, Ak, Ck, Av, Cv,
                                           hh, hl, hh + HSTRIDE, hl + HSTRIDE,
                                           hh + 2 * HSTRIDE, hl + 2 * HSTRIDE);
    // presplit x
    pack_act<<<(ROWS * EMB / 4) / 256, 256>>>(x, ah, al);
    // projections
    gemm_mma<<<ggrid, 256, GSM_BYTES>>>(ah, al, hh, hl, wh, wl, bq, q);
    gemm_mma<<<ggrid, 256, GSM_BYTES>>>(ah, al, hh + HSTRIDE, hl + HSTRIDE,
                                        wh + WSTRIDE, wl + WSTRIDE, bk, k);
    gemm_mma<<<ggrid, 256, GSM_BYTES>>>(ah, al, hh + 2 * HSTRIDE, hl + 2 * HSTRIDE,
                                        wh + 2 * WSTRIDE, wl + 2 * WSTRIDE, bv, v);
    // rope
    rope_kernel<<<(ROWS * NHEAD * 64 + 255) / 256, 256>>>(q, k);
    // flash attention
    flash_mma<<<dim3(SEQ / 128, BATCH * NHEAD), 256, FA2_SMEM>>>(q, k, v, att);
    // output projection
    aux_gemm<<<dim3(1, ROWS / 128), 256>>>(att, mask, Ao, Co, Ao, Co, Ao, Co,
                                           hh + 3 * HSTRIDE, hl + 3 * HSTRIDE,
                                           hh + 3 * HSTRIDE, hl + 3 * HSTRIDE,
                                           hh + 3 * HSTRIDE, hl + 3 * HSTRIDE);
    pack_act<<<(ROWS * EMB / 4) / 256, 256>>>(att, ah, al);
    gemm_mma<<<ggrid, 256, GSM_BYTES>>>(ah, al, hh + 3 * HSTRIDE, hl + 3 * HSTRIDE,
                                        wh + 3 * WSTRIDE, wl + 3 * WSTRIDE,
                                        nullptr, (float*)d_out);
}